// round 13
// baseline (speedup 1.0000x reference)
#include <cuda_runtime.h>
#include <cuda_fp16.h>

#define NTHR   256
#define KKB    288
#define EPS    1e-6f
#define LAM    1e-3f
#define LN2PI  1.8378770664093453f
#define LOG2E  1.4426950408889634f

// shared-memory float offsets
#define SM_POSE 0                       // 288*32 dup-packed = 9216
#define SM_ACT  (KKB*32)                // 9216, size 288
#define SM_RED  (SM_ACT + KKB)         // 9504, 33*257 = 8481 -> ends 17985
#define SM_NMU  (SM_RED + 33*257 + 1)  // 17986 (even), 32*18 = 576
#define SM_ABT  (SM_NMU + 576)         // 18562 -> pad to 16B
#define SM_ABT16 ((SM_ABT + 3) & ~3)   // 18564 (16B-aligned), 1024 floats: [pp][c]{A2,B2}
#define SM_AOUT (SM_ABT16 + 1024)      // 19588, 32
#define SM_CC2  (SM_AOUT + 32)         // 19620, 32
#define SM_TOTAL (SM_CC2 + 32)         // 19652 floats = 78608 bytes

// fp16 transposed weights: uint4 index = n*64 + qp*32 + c
// uint4 = 8 halves: {q=2qp: cols 0,1 | cols 2,3 ; q=2qp+1: cols 0,1 | cols 2,3}
__device__ uint4 g_wth4[18432];

__global__ void transpose_w_kernel(const float* __restrict__ w) {
    int t = blockIdx.x * 256 + threadIdx.x;
    if (t < 18432) {
        int n = t >> 6, r = t & 63, qp = r >> 5, c = r & 31;
        const float* s = w + n * 512 + c * 16 + qp * 8;
        __half2 h0 = __floats2half2_rn(s[0], s[1]);
        __half2 h1 = __floats2half2_rn(s[2], s[3]);
        __half2 h2 = __floats2half2_rn(s[4], s[5]);
        __half2 h3 = __floats2half2_rn(s[6], s[7]);
        uint4 o;
        o.x = *reinterpret_cast<unsigned*>(&h0);
        o.y = *reinterpret_cast<unsigned*>(&h1);
        o.z = *reinterpret_cast<unsigned*>(&h2);
        o.w = *reinterpret_cast<unsigned*>(&h3);
        g_wth4[t] = o;
    }
}

// ---------- packed f32x2 primitives ----------
typedef unsigned long long u64;

__device__ __forceinline__ u64 fma2(u64 a, u64 b, u64 c) {
    u64 d; asm("fma.rn.f32x2 %0, %1, %2, %3;" : "=l"(d) : "l"(a), "l"(b), "l"(c));
    return d;
}
__device__ __forceinline__ u64 mul2(u64 a, u64 b) {
    u64 d; asm("mul.rn.f32x2 %0, %1, %2;" : "=l"(d) : "l"(a), "l"(b));
    return d;
}
__device__ __forceinline__ u64 add2(u64 a, u64 b) {
    u64 d; asm("add.rn.f32x2 %0, %1, %2;" : "=l"(d) : "l"(a), "l"(b));
    return d;
}
__device__ __forceinline__ u64 pack2(float lo, float hi) {
    u64 r; asm("mov.b64 %0, {%1, %2};" : "=l"(r) : "f"(lo), "f"(hi)); return r;
}
__device__ __forceinline__ float2 unpack2(u64 v) {
    float2 r; asm("mov.b64 {%0, %1}, %2;" : "=f"(r.x), "=f"(r.y) : "l"(v)); return r;
}
__device__ __forceinline__ u64 h2u64(unsigned h) {
    __half2 hh = *reinterpret_cast<__half2*>(&h);
    float2 f = __half22float2(hh);
    return pack2(f.x, f.y);
}

// warp max of a float via integer redux (order-preserving u32 mapping)
__device__ __forceinline__ float redmax32f(float v) {
    int i = __float_as_int(v);
    unsigned u = (unsigned)(i ^ ((i >> 31) | 0x80000000));
    unsigned m;
    asm("redux.sync.max.u32 %0, %1, 0xffffffff;" : "=r"(m) : "r"(u));
    int mi = (int)(m ^ ((~(int)m >> 31) | 0x80000000));
    return __int_as_float(mi);
}

// warp sum of e in [0,1] via fixed-point redux (scale 2^23; max sum 2^28, no overflow)
__device__ __forceinline__ float redsum01(float e) {
    unsigned q = (unsigned)__float2uint_rn(e * 8388608.f);
    unsigned t;
    asm("redux.sync.add.u32 %0, %1, 0xffffffff;" : "=r"(t) : "r"(q));
    return (float)t * (1.0f / 8388608.f);
}

// v pairs from fp16 weights (converted in-register) + dup-packed pose (broadcast LDS)
__device__ __forceinline__ void compute_v2(const float* __restrict__ sm, int n, int c,
                                           u64* __restrict__ v2) {
    const uint4* __restrict__ W = g_wth4 + n * 64 + c;
    uint4 wa = W[0], wb = W[32];
    u64 w0x = h2u64(wa.x), w0y = h2u64(wa.y);
    u64 w1x = h2u64(wa.z), w1y = h2u64(wa.w);
    u64 w2x = h2u64(wb.x), w2y = h2u64(wb.y);
    u64 w3x = h2u64(wb.z), w3y = h2u64(wb.w);
    const ulonglong2* __restrict__ P = (const ulonglong2*)(sm + SM_POSE + n * 32);
    #pragma unroll
    for (int i = 0; i < 4; ++i) {
        ulonglong2 pa = P[2 * i];
        ulonglong2 pb = P[2 * i + 1];
        v2[2*i]   = fma2(pa.x, w0x, fma2(pa.y, w1x, fma2(pb.x, w2x, mul2(pb.y, w3x))));
        v2[2*i+1] = fma2(pa.x, w0y, fma2(pa.y, w1y, fma2(pb.x, w2y, mul2(pb.y, w3y))));
    }
}

// paired quadratic-form distance (log2 domain): A,B loaded ONCE, used for both chains
__device__ __forceinline__ void dist_pair(const u64* __restrict__ va,
                                          const u64* __restrict__ vb,
                                          const float* __restrict__ sm, int c,
                                          float& d0, float& d1) {
    u64 acc0 = 0ull, acc1 = 0ull;
    #pragma unroll
    for (int pp = 0; pp < 8; ++pp) {
        ulonglong2 ab = *(const ulonglong2*)(sm + SM_ABT16 + 4 * (pp * 32 + c));
        acc0 = fma2(va[pp], fma2(ab.x, va[pp], ab.y), acc0);
        acc1 = fma2(vb[pp], fma2(ab.x, vb[pp], ab.y), acc1);
    }
    float2 f0 = unpack2(acc0), f1 = unpack2(acc1);
    d0 = f0.x + f0.y;
    d1 = f1.x + f1.y;
}

__device__ __forceinline__ void macc2(float r, const u64* __restrict__ v2,
                                      u64* __restrict__ S1, u64* __restrict__ S2) {
    u64 r2 = pack2(r, r);
    #pragma unroll
    for (int pp = 0; pp < 8; ++pp) {
        u64 rv = mul2(r2, v2[pp]);
        S1[pp] = add2(S1[pp], rv);
        S2[pp] = fma2(rv, v2[pp], S2[pp]);
    }
}

__device__ __forceinline__ void store_red(float* __restrict__ sm, int warp, int c,
                                          const u64* __restrict__ S1,
                                          const u64* __restrict__ S2, float rs) {
    float* base = sm + SM_RED + warp * 32 + c;
    #pragma unroll
    for (int pp = 0; pp < 8; ++pp) {
        float2 a = unpack2(S1[pp]);
        float2 b = unpack2(S2[pp]);
        base[(2*pp)    * 257] = a.x;
        base[(2*pp+1)  * 257] = a.y;
        base[(2*pp+16) * 257] = b.x;
        base[(2*pp+17) * 257] = b.y;
    }
    base[32 * 257] = rs;
}

// parallel finalize: 32 groups of 8 lanes; group g = capsule c, lane handles p=2l8,2l8+1
__device__ __forceinline__ void finalize(float* __restrict__ sm, int tid,
                                         const float* __restrict__ gbu,
                                         const float* __restrict__ gba) {
    const int g = tid >> 3, l8 = tid & 7;
    float rsum = 0.f;
    #pragma unroll
    for (int w = 0; w < 8; ++w) rsum += sm[SM_RED + 32 * 257 + w * 32 + g];
    float inv = __fdividef(1.0f, rsum + EPS);
    float nmu[2], isg[2], plog = 0.f, cpart = 0.f;
    #pragma unroll
    for (int t = 0; t < 2; ++t) {
        int p = 2 * l8 + t;
        float s1 = 0.f, s2 = 0.f;
        #pragma unroll
        for (int w = 0; w < 8; ++w) {
            s1 += sm[SM_RED + p * 257        + w * 32 + g];
            s2 += sm[SM_RED + (p + 16) * 257 + w * 32 + g];
        }
        float mu = s1 * inv;
        float sg = (s2 - 2.f * mu * s1 + mu * mu * rsum) * inv + EPS;
        sm[SM_NMU + g * 18 + p] = -mu;
        nmu[t] = -mu;
        isg[t] = __fdividef(0.5f, sg);
        plog  += __logf(sg);
        cpart  = fmaf(isg[t] * nmu[t], nmu[t], cpart);
    }
    {
        ulonglong2 ab;
        ab.x = pack2(isg[0] * LOG2E, isg[1] * LOG2E);
        ab.y = pack2(2.f * isg[0] * nmu[0] * LOG2E, 2.f * isg[1] * nmu[1] * LOG2E);
        *(ulonglong2*)(sm + SM_ABT16 + 4 * (l8 * 32 + g)) = ab;
    }
    #pragma unroll
    for (int d = 1; d < 8; d <<= 1) {
        plog  += __shfl_xor_sync(0xffffffffu, plog, d);
        cpart += __shfl_xor_sync(0xffffffffu, cpart, d);
    }
    if (l8 == 0) {
        float cost = rsum * (16.f * gbu[g] + 0.5f * plog);
        float ao = __fdividef(1.f, 1.f + __expf(LAM * (cost - gba[g])));
        sm[SM_AOUT + g] = ao;
        sm[SM_CC2 + g]  = LOG2E * (__logf(ao) - 0.5f * plog - 8.f * LN2PI - cpart);
    }
}

__global__ void __launch_bounds__(NTHR, 2)
convcaps_kernel(const float* __restrict__ gx, const float* __restrict__ ga,
                const float* __restrict__ gbu, const float* __restrict__ gba,
                float* __restrict__ gout)
{
    extern __shared__ float sm[];
    const int tid  = threadIdx.x;
    const int warp = tid >> 5;
    const int c    = tid & 31;
    const int blk  = blockIdx.x;           // b*36 + h*6 + w
    const int b    = blk / 36;
    const int hw   = blk - b * 36;
    const int h2   = (hw / 6) * 2;
    const int w2   = (hw % 6) * 2;

    // ---- load pose patch duplicated: row n = [p0,p0,p1,p1,...,p15,p15] ----
    for (int idx = tid; idx < KKB * 16; idx += NTHR) {
        int n = idx >> 4, q = idx & 15;
        int ki = n / 96; int rem = n - ki * 96;
        int kj = rem >> 5; int bi = rem & 31;
        float f = gx[(size_t)((b * 14 + h2 + ki) * 14 + (w2 + kj)) * 512 + bi * 16 + q];
        *(float2*)(sm + SM_POSE + n * 32 + 2 * q) = make_float2(f, f);
    }
    for (int n = tid; n < KKB; n += NTHR) {
        int ki = n / 96; int rem = n - ki * 96;
        int kj = rem >> 5; int bi = rem & 31;
        sm[SM_ACT + n] = ga[((b * 14 + h2 + ki) * 14 + (w2 + kj)) * 32 + bi];
    }
    __syncthreads();

    u64 S1[8], S2[8];
    float rs;
    const int phase = 4 * warp;            // stagger warps' memory bursts

    // ================= pass 0: M-step with uniform r = act/32 =================
    #pragma unroll
    for (int pp = 0; pp < 8; ++pp) { S1[pp] = 0ull; S2[pp] = 0ull; }
    rs = 0.f;
    for (int t = 0; t < 36; t += 2) {
        int i = t + phase; if (i >= 36) i -= 36;
        int n0 = warp + 8 * i, n1 = n0 + 8;
        u64 va[8], vb[8];
        compute_v2(sm, n0, c, va);
        compute_v2(sm, n1, c, vb);
        float r0 = sm[SM_ACT + n0] * (1.0f / 32.0f);
        float r1 = sm[SM_ACT + n1] * (1.0f / 32.0f);
        rs += r0 + r1;
        macc2(r0, va, S1, S2);
        macc2(r1, vb, S1, S2);
    }
    store_red(sm, warp, c, S1, S2, rs);
    __syncthreads();
    finalize(sm, tid, gbu, gba);
    __syncthreads();

    // ================= 2 fused E+M passes (2-way interleaved, shared A/B) =======
    for (int it = 0; it < 2; ++it) {
        const float ccst2 = sm[SM_CC2 + c];
        #pragma unroll
        for (int pp = 0; pp < 8; ++pp) { S1[pp] = 0ull; S2[pp] = 0ull; }
        rs = 0.f;

        for (int t = 0; t < 36; t += 2) {
            int i = t + phase; if (i >= 36) i -= 36;
            int n0 = warp + 8 * i, n1 = n0 + 8;
            u64 va[8], vb[8];
            compute_v2(sm, n0, c, va);
            compute_v2(sm, n1, c, vb);
            float d0, d1;
            dist_pair(va, vb, sm, c, d0, d1);
            float l0 = ccst2 - d0;                 // log2 domain
            float l1 = ccst2 - d1;
            float m0 = redmax32f(l0);
            float m1 = redmax32f(l1);
            float e0 = exp2f(l0 - m0);
            float e1 = exp2f(l1 - m1);
            float s0 = redsum01(e0);
            float s1 = redsum01(e1);
            float r0 = __fdividef(e0, s0);
            float r1 = __fdividef(e1, s1);
            rs += r0 + r1;
            macc2(r0, va, S1, S2);
            macc2(r1, vb, S1, S2);
        }
        store_red(sm, warp, c, S1, S2, rs);
        __syncthreads();
        finalize(sm, tid, gbu, gba);
        __syncthreads();
    }

    // ---- outputs: p_out (288*512 floats) then a_out (288*32 floats) ----
    for (int idx = tid; idx < 512; idx += NTHR) {
        int co = idx >> 4, p = idx & 15;
        gout[(size_t)blk * 512 + idx] = -sm[SM_NMU + co * 18 + p];
    }
    if (tid < 32)
        gout[147456 + blk * 32 + tid] = sm[SM_AOUT + tid];
}

extern "C" void kernel_launch(void* const* d_in, const int* in_sizes, int n_in,
                              void* d_out, int out_size) {
    const float* x  = (const float*)d_in[0];
    const float* a  = (const float*)d_in[1];
    const float* w  = (const float*)d_in[2];
    const float* bu = (const float*)d_in[3];
    const float* ba = (const float*)d_in[4];
    float* out = (float*)d_out;
    (void)in_sizes; (void)n_in; (void)out_size;

    transpose_w_kernel<<<72, 256>>>(w);

    const int smem_bytes = SM_TOTAL * (int)sizeof(float);  // 78608 B
    cudaFuncSetAttribute(convcaps_kernel,
                         cudaFuncAttributeMaxDynamicSharedMemorySize, smem_bytes);
    convcaps_kernel<<<288, NTHR, smem_bytes>>>(x, a, bu, ba, out);
}

// round 14
// speedup vs baseline: 1.0574x; 1.0574x over previous
#include <cuda_runtime.h>

#define NTHR   256
#define KKB    288
#define EPS    1e-6f
#define LAM    1e-3f
#define LN2PI  1.8378770664093453f
#define LOG2E  1.4426950408889634f

// shared-memory float offsets
#define SM_POSE 0                       // 288*32 dup-packed = 9216
#define SM_ACT  (KKB*32)                // 9216, size 288
#define SM_RED  (SM_ACT + KKB)         // 9504, 33*257 = 8481 -> ends 17985
#define SM_NMU  (SM_RED + 33*257 + 1)  // 17986 (even), 32*18 = 576
#define SM_ABT  (SM_NMU + 576)         // 18562 -> pad to 16B
#define SM_ABT16 ((SM_ABT + 3) & ~3)   // 18564 (16B-aligned), 1024 floats: [pp][c]{A2,B2}
#define SM_AOUT (SM_ABT16 + 1024)      // 19588, 32
#define SM_CC2  (SM_AOUT + 32)         // 19620, 32
#define SM_TOTAL (SM_CC2 + 32)         // 19652 floats = 78608 bytes

// transposed fp32 weights: float4 index = n*128 + q*32 + c  (q = row of W_nc)
__device__ float4 g_wt[36864];

__global__ void transpose_w_kernel(const float* __restrict__ w) {
    int j = blockIdx.x * 256 + threadIdx.x;
    if (j < 147456) {
        int n = j >> 9, r = j & 511;
        int q = r >> 7, c = (r >> 2) & 31, e = r & 3;
        ((float*)g_wt)[j] = w[n * 512 + c * 16 + q * 4 + e];
    }
}

// ---------- packed f32x2 primitives ----------
typedef unsigned long long u64;

__device__ __forceinline__ u64 fma2(u64 a, u64 b, u64 c) {
    u64 d; asm("fma.rn.f32x2 %0, %1, %2, %3;" : "=l"(d) : "l"(a), "l"(b), "l"(c));
    return d;
}
__device__ __forceinline__ u64 mul2(u64 a, u64 b) {
    u64 d; asm("mul.rn.f32x2 %0, %1, %2;" : "=l"(d) : "l"(a), "l"(b));
    return d;
}
__device__ __forceinline__ u64 add2(u64 a, u64 b) {
    u64 d; asm("add.rn.f32x2 %0, %1, %2;" : "=l"(d) : "l"(a), "l"(b));
    return d;
}
__device__ __forceinline__ u64 pack2(float lo, float hi) {
    u64 r; asm("mov.b64 %0, {%1, %2};" : "=l"(r) : "f"(lo), "f"(hi)); return r;
}
__device__ __forceinline__ float2 unpack2(u64 v) {
    float2 r; asm("mov.b64 {%0, %1}, %2;" : "=f"(r.x), "=f"(r.y) : "l"(v)); return r;
}

// warp max of a float via integer redux (order-preserving u32 mapping)
__device__ __forceinline__ float redmax32f(float v) {
    int i = __float_as_int(v);
    unsigned u = (unsigned)(i ^ ((i >> 31) | 0x80000000));
    unsigned m;
    asm("redux.sync.max.u32 %0, %1, 0xffffffff;" : "=r"(m) : "r"(u));
    int mi = (int)(m ^ ((~(int)m >> 31) | 0x80000000));
    return __int_as_float(mi);
}

// warp sum of e in [0,1] via fixed-point redux (scale 2^23; max sum 2^28, no overflow)
__device__ __forceinline__ float redsum01(float e) {
    unsigned q = (unsigned)__float2uint_rn(e * 8388608.f);
    unsigned t;
    asm("redux.sync.add.u32 %0, %1, 0xffffffff;" : "=r"(t) : "r"(q));
    return (float)t * (1.0f / 8388608.f);
}

// load weights for row n (this lane's c slice): 4 ulonglong2 = 16 regs
__device__ __forceinline__ void load_w(ulonglong2* __restrict__ w, int n, int c) {
    const ulonglong2* __restrict__ W = (const ulonglong2*)g_wt + ((size_t)n * 128 + c);
    w[0] = W[0]; w[1] = W[32]; w[2] = W[64]; w[3] = W[96];
}

// v from register weights + dup-packed pose row (broadcast LDS)
__device__ __forceinline__ void compute_v2r(const ulonglong2* __restrict__ w,
                                            const float* __restrict__ poserow,
                                            u64* __restrict__ v2) {
    const ulonglong2* __restrict__ P = (const ulonglong2*)poserow;
    #pragma unroll
    for (int i = 0; i < 4; ++i) {
        ulonglong2 pa = P[2 * i];
        ulonglong2 pb = P[2 * i + 1];
        v2[2*i]   = fma2(pa.x, w[0].x, fma2(pa.y, w[1].x, fma2(pb.x, w[2].x, mul2(pb.y, w[3].x))));
        v2[2*i+1] = fma2(pa.x, w[0].y, fma2(pa.y, w[1].y, fma2(pb.x, w[2].y, mul2(pb.y, w[3].y))));
    }
}

// quadratic-form distance (log2 domain): dist = sum_p A_p v^2 + B_p v
__device__ __forceinline__ float dist16ab(const u64* __restrict__ v2,
                                          const float* __restrict__ sm, int c) {
    u64 acc = 0ull;
    #pragma unroll
    for (int pp = 0; pp < 8; ++pp) {
        ulonglong2 ab = *(const ulonglong2*)(sm + SM_ABT16 + 4 * (pp * 32 + c));
        acc = fma2(v2[pp], fma2(ab.x, v2[pp], ab.y), acc);
    }
    float2 df = unpack2(acc);
    return df.x + df.y;
}

__device__ __forceinline__ void macc2(float r, const u64* __restrict__ v2,
                                      u64* __restrict__ S1, u64* __restrict__ S2) {
    u64 r2 = pack2(r, r);
    #pragma unroll
    for (int pp = 0; pp < 8; ++pp) {
        u64 rv = mul2(r2, v2[pp]);
        S1[pp] = add2(S1[pp], rv);
        S2[pp] = fma2(rv, v2[pp], S2[pp]);
    }
}

__device__ __forceinline__ void store_red(float* __restrict__ sm, int warp, int c,
                                          const u64* __restrict__ S1,
                                          const u64* __restrict__ S2, float rs) {
    float* base = sm + SM_RED + warp * 32 + c;
    #pragma unroll
    for (int pp = 0; pp < 8; ++pp) {
        float2 a = unpack2(S1[pp]);
        float2 b = unpack2(S2[pp]);
        base[(2*pp)    * 257] = a.x;
        base[(2*pp+1)  * 257] = a.y;
        base[(2*pp+16) * 257] = b.x;
        base[(2*pp+17) * 257] = b.y;
    }
    base[32 * 257] = rs;
}

// parallel finalize: 32 groups of 8 lanes; group g = capsule c, lane handles p=2l8,2l8+1
__device__ __forceinline__ void finalize(float* __restrict__ sm, int tid,
                                         const float* __restrict__ gbu,
                                         const float* __restrict__ gba) {
    const int g = tid >> 3, l8 = tid & 7;
    float rsum = 0.f;
    #pragma unroll
    for (int w = 0; w < 8; ++w) rsum += sm[SM_RED + 32 * 257 + w * 32 + g];
    float inv = __fdividef(1.0f, rsum + EPS);
    float nmu[2], isg[2], plog = 0.f, cpart = 0.f;
    #pragma unroll
    for (int t = 0; t < 2; ++t) {
        int p = 2 * l8 + t;
        float s1 = 0.f, s2 = 0.f;
        #pragma unroll
        for (int w = 0; w < 8; ++w) {
            s1 += sm[SM_RED + p * 257        + w * 32 + g];
            s2 += sm[SM_RED + (p + 16) * 257 + w * 32 + g];
        }
        float mu = s1 * inv;
        float sg = (s2 - 2.f * mu * s1 + mu * mu * rsum) * inv + EPS;
        sm[SM_NMU + g * 18 + p] = -mu;
        nmu[t] = -mu;
        isg[t] = __fdividef(0.5f, sg);
        plog  += __logf(sg);
        cpart  = fmaf(isg[t] * nmu[t], nmu[t], cpart);
    }
    {
        ulonglong2 ab;
        ab.x = pack2(isg[0] * LOG2E, isg[1] * LOG2E);
        ab.y = pack2(2.f * isg[0] * nmu[0] * LOG2E, 2.f * isg[1] * nmu[1] * LOG2E);
        *(ulonglong2*)(sm + SM_ABT16 + 4 * (l8 * 32 + g)) = ab;
    }
    #pragma unroll
    for (int d = 1; d < 8; d <<= 1) {
        plog  += __shfl_xor_sync(0xffffffffu, plog, d);
        cpart += __shfl_xor_sync(0xffffffffu, cpart, d);
    }
    if (l8 == 0) {
        float cost = rsum * (16.f * gbu[g] + 0.5f * plog);
        float ao = __fdividef(1.f, 1.f + __expf(LAM * (cost - gba[g])));
        sm[SM_AOUT + g] = ao;
        sm[SM_CC2 + g]  = LOG2E * (__logf(ao) - 0.5f * plog - 8.f * LN2PI - cpart);
    }
}

// staggered n index: i = (t + phase) mod 36 (valid for t+phase < 72)
__device__ __forceinline__ int nidx(int t, int phase, int warp) {
    int i = t + phase; if (i >= 36) i -= 36;
    return warp + 8 * i;
}

__global__ void __launch_bounds__(NTHR, 2)
convcaps_kernel(const float* __restrict__ gx, const float* __restrict__ ga,
                const float* __restrict__ gbu, const float* __restrict__ gba,
                float* __restrict__ gout)
{
    extern __shared__ float sm[];
    const int tid  = threadIdx.x;
    const int warp = tid >> 5;
    const int c    = tid & 31;
    const int blk  = blockIdx.x;           // b*36 + h*6 + w
    const int b    = blk / 36;
    const int hw   = blk - b * 36;
    const int h2   = (hw / 6) * 2;
    const int w2   = (hw % 6) * 2;

    // ---- load pose patch duplicated: row n = [p0,p0,p1,p1,...,p15,p15] ----
    for (int idx = tid; idx < KKB * 16; idx += NTHR) {
        int n = idx >> 4, q = idx & 15;
        int ki = n / 96; int rem = n - ki * 96;
        int kj = rem >> 5; int bi = rem & 31;
        float f = gx[(size_t)((b * 14 + h2 + ki) * 14 + (w2 + kj)) * 512 + bi * 16 + q];
        *(float2*)(sm + SM_POSE + n * 32 + 2 * q) = make_float2(f, f);
    }
    for (int n = tid; n < KKB; n += NTHR) {
        int ki = n / 96; int rem = n - ki * 96;
        int kj = rem >> 5; int bi = rem & 31;
        sm[SM_ACT + n] = ga[((b * 14 + h2 + ki) * 14 + (w2 + kj)) * 32 + bi];
    }
    __syncthreads();

    u64 S1[8], S2[8];
    float rs;
    ulonglong2 wA[4], wB[4];
    const int phase = 4 * warp;            // stagger warps' memory bursts

    // ================= pass 0: M-step with uniform r = act/32 =================
    #pragma unroll
    for (int pp = 0; pp < 8; ++pp) { S1[pp] = 0ull; S2[pp] = 0ull; }
    rs = 0.f;
    load_w(wA, nidx(0, phase, warp), c);
    for (int t = 0; t < 36; t += 2) {
        load_w(wB, nidx(t + 1, phase, warp), c);     // prefetch next
        {
            int n = nidx(t, phase, warp);
            u64 v2[8];
            compute_v2r(wA, sm + SM_POSE + n * 32, v2);
            float r = sm[SM_ACT + n] * (1.0f / 32.0f);
            rs += r;
            macc2(r, v2, S1, S2);
        }
        load_w(wA, nidx(t + 2, phase, warp), c);     // prefetch next (wraps at end)
        {
            int n = nidx(t + 1, phase, warp);
            u64 v2[8];
            compute_v2r(wB, sm + SM_POSE + n * 32, v2);
            float r = sm[SM_ACT + n] * (1.0f / 32.0f);
            rs += r;
            macc2(r, v2, S1, S2);
        }
    }
    store_red(sm, warp, c, S1, S2, rs);
    __syncthreads();
    finalize(sm, tid, gbu, gba);
    __syncthreads();

    // ================= 2 fused E+M passes (software-pipelined weights) ==========
    for (int it = 0; it < 2; ++it) {
        const float ccst2 = sm[SM_CC2 + c];
        #pragma unroll
        for (int pp = 0; pp < 8; ++pp) { S1[pp] = 0ull; S2[pp] = 0ull; }
        rs = 0.f;
        load_w(wA, nidx(0, phase, warp), c);

        for (int t = 0; t < 36; t += 2) {
            load_w(wB, nidx(t + 1, phase, warp), c);   // prefetch: covered by body
            {
                int n = nidx(t, phase, warp);
                u64 v2[8];
                compute_v2r(wA, sm + SM_POSE + n * 32, v2);
                float l = ccst2 - dist16ab(v2, sm, c);   // log2 domain
                float m = redmax32f(l);
                float e = exp2f(l - m);
                float s = redsum01(e);
                float r = __fdividef(e, s);
                rs += r;
                macc2(r, v2, S1, S2);
            }
            load_w(wA, nidx(t + 2, phase, warp), c);   // prefetch (wraps at end)
            {
                int n = nidx(t + 1, phase, warp);
                u64 v2[8];
                compute_v2r(wB, sm + SM_POSE + n * 32, v2);
                float l = ccst2 - dist16ab(v2, sm, c);
                float m = redmax32f(l);
                float e = exp2f(l - m);
                float s = redsum01(e);
                float r = __fdividef(e, s);
                rs += r;
                macc2(r, v2, S1, S2);
            }
        }
        store_red(sm, warp, c, S1, S2, rs);
        __syncthreads();
        finalize(sm, tid, gbu, gba);
        __syncthreads();
    }

    // ---- outputs: p_out (288*512 floats) then a_out (288*32 floats) ----
    for (int idx = tid; idx < 512; idx += NTHR) {
        int co = idx >> 4, p = idx & 15;
        gout[(size_t)blk * 512 + idx] = -sm[SM_NMU + co * 18 + p];
    }
    if (tid < 32)
        gout[147456 + blk * 32 + tid] = sm[SM_AOUT + tid];
}

extern "C" void kernel_launch(void* const* d_in, const int* in_sizes, int n_in,
                              void* d_out, int out_size) {
    const float* x  = (const float*)d_in[0];
    const float* a  = (const float*)d_in[1];
    const float* w  = (const float*)d_in[2];
    const float* bu = (const float*)d_in[3];
    const float* ba = (const float*)d_in[4];
    float* out = (float*)d_out;
    (void)in_sizes; (void)n_in; (void)out_size;

    transpose_w_kernel<<<576, 256>>>(w);

    const int smem_bytes = SM_TOTAL * (int)sizeof(float);  // 78608 B
    cudaFuncSetAttribute(convcaps_kernel,
                         cudaFuncAttributeMaxDynamicSharedMemorySize, smem_bytes);
    convcaps_kernel<<<288, NTHR, smem_bytes>>>(x, a, bu, ba, out);
}

// round 15
// speedup vs baseline: 1.0646x; 1.0068x over previous
#include <cuda_runtime.h>

#define NTHR   256
#define KKB    288
#define EPS    1e-6f
#define LAM    1e-3f
#define LN2PI  1.8378770664093453f
#define LOG2E  1.4426950408889634f

// shared-memory float offsets
#define SM_POSE 0                       // 288*32 dup-packed = 9216
#define SM_ACT  (KKB*32)                // 9216, size 288
#define SM_RED  (SM_ACT + KKB)         // 9504, 33*257 = 8481 -> ends 17985
#define SM_NMU  (SM_RED + 33*257 + 1)  // 17986 (even), 32*18 = 576
#define SM_AT   (SM_NMU + 576)         // 18562 (8B-aligned), 512 floats: u64[pp*32+c]
#define SM_BT   (SM_AT + 512)          // 19074, 512
#define SM_AOUT (SM_BT + 512)          // 19586, 32
#define SM_CC2  (SM_AOUT + 32)         // 19618, 32
#define SM_TOTAL (SM_CC2 + 32)         // 19650 floats = 78600 bytes

// transposed fp32 weights: float4 index = n*128 + q*32 + c  (q = row of W_nc)
__device__ float4 g_wt[36864];

__global__ void transpose_w_kernel(const float* __restrict__ w) {
    int j = blockIdx.x * 256 + threadIdx.x;
    if (j < 147456) {
        int n = j >> 9, r = j & 511;
        int q = r >> 7, c = (r >> 2) & 31, e = r & 3;
        ((float*)g_wt)[j] = w[n * 512 + c * 16 + q * 4 + e];
    }
}

// ---------- packed f32x2 primitives ----------
typedef unsigned long long u64;

__device__ __forceinline__ u64 fma2(u64 a, u64 b, u64 c) {
    u64 d; asm("fma.rn.f32x2 %0, %1, %2, %3;" : "=l"(d) : "l"(a), "l"(b), "l"(c));
    return d;
}
__device__ __forceinline__ u64 mul2(u64 a, u64 b) {
    u64 d; asm("mul.rn.f32x2 %0, %1, %2;" : "=l"(d) : "l"(a), "l"(b));
    return d;
}
__device__ __forceinline__ u64 add2(u64 a, u64 b) {
    u64 d; asm("add.rn.f32x2 %0, %1, %2;" : "=l"(d) : "l"(a), "l"(b));
    return d;
}
__device__ __forceinline__ u64 pack2(float lo, float hi) {
    u64 r; asm("mov.b64 %0, {%1, %2};" : "=l"(r) : "f"(lo), "f"(hi)); return r;
}
__device__ __forceinline__ float2 unpack2(u64 v) {
    float2 r; asm("mov.b64 {%0, %1}, %2;" : "=f"(r.x), "=f"(r.y) : "l"(v)); return r;
}

// warp max of a float via integer redux (order-preserving u32 mapping)
__device__ __forceinline__ float redmax32f(float v) {
    int i = __float_as_int(v);
    unsigned u = (unsigned)(i ^ ((i >> 31) | 0x80000000));
    unsigned m;
    asm("redux.sync.max.u32 %0, %1, 0xffffffff;" : "=r"(m) : "r"(u));
    int mi = (int)(m ^ ((~(int)m >> 31) | 0x80000000));
    return __int_as_float(mi);
}

// warp sum of e in [0,1] via fixed-point redux (scale 2^23; max sum 2^28, no overflow)
__device__ __forceinline__ float redsum01(float e) {
    unsigned q = (unsigned)__float2uint_rn(e * 8388608.f);
    unsigned t;
    asm("redux.sync.add.u32 %0, %1, 0xffffffff;" : "=r"(t) : "r"(q));
    return (float)t * (1.0f / 8388608.f);
}

// v pairs: v2[2i] = (v[4i+0], v[4i+1]), v2[2i+1] = (v[4i+2], v[4i+3])
__device__ __forceinline__ void compute_v2(const float* __restrict__ sm, int n, int c,
                                           u64* __restrict__ v2) {
    const ulonglong2* __restrict__ W = (const ulonglong2*)g_wt + ((size_t)n * 128 + c);
    ulonglong2 w0 = W[0], w1 = W[32], w2 = W[64], w3 = W[96];
    const ulonglong2* __restrict__ P = (const ulonglong2*)(sm + SM_POSE + n * 32);
    #pragma unroll
    for (int i = 0; i < 4; ++i) {
        ulonglong2 pa = P[2 * i];
        ulonglong2 pb = P[2 * i + 1];
        v2[2*i]   = fma2(pa.x, w0.x, fma2(pa.y, w1.x, fma2(pb.x, w2.x, mul2(pb.y, w3.x))));
        v2[2*i+1] = fma2(pa.x, w0.y, fma2(pa.y, w1.y, fma2(pb.x, w2.y, mul2(pb.y, w3.y))));
    }
}

// paired quadratic-form distance (log2 domain) with REGISTER-resident A,B tables
__device__ __forceinline__ void dist_pair_r(const u64* __restrict__ va,
                                            const u64* __restrict__ vb,
                                            const u64* __restrict__ Ar,
                                            const u64* __restrict__ Br,
                                            float& d0, float& d1) {
    u64 acc0 = 0ull, acc1 = 0ull;
    #pragma unroll
    for (int pp = 0; pp < 8; ++pp) {
        acc0 = fma2(va[pp], fma2(Ar[pp], va[pp], Br[pp]), acc0);
        acc1 = fma2(vb[pp], fma2(Ar[pp], vb[pp], Br[pp]), acc1);
    }
    float2 f0 = unpack2(acc0), f1 = unpack2(acc1);
    d0 = f0.x + f0.y;
    d1 = f1.x + f1.y;
}

__device__ __forceinline__ void macc2(float r, const u64* __restrict__ v2,
                                      u64* __restrict__ S1, u64* __restrict__ S2) {
    u64 r2 = pack2(r, r);
    #pragma unroll
    for (int pp = 0; pp < 8; ++pp) {
        u64 rv = mul2(r2, v2[pp]);
        S1[pp] = add2(S1[pp], rv);
        S2[pp] = fma2(rv, v2[pp], S2[pp]);
    }
}

__device__ __forceinline__ void store_red(float* __restrict__ sm, int warp, int c,
                                          const u64* __restrict__ S1,
                                          const u64* __restrict__ S2, float rs) {
    float* base = sm + SM_RED + warp * 32 + c;
    #pragma unroll
    for (int pp = 0; pp < 8; ++pp) {
        float2 a = unpack2(S1[pp]);
        float2 b = unpack2(S2[pp]);
        base[(2*pp)    * 257] = a.x;
        base[(2*pp+1)  * 257] = a.y;
        base[(2*pp+16) * 257] = b.x;
        base[(2*pp+17) * 257] = b.y;
    }
    base[32 * 257] = rs;
}

// parallel finalize: 32 groups of 8 lanes; group g = capsule c, lane handles p=2l8,2l8+1
// Produces: SM_NMU (output), SM_AT/SM_BT (log2-domain A,B tables, u64[pp*32+c]),
//           SM_CC2 = log2e*(ln(a_out) - 0.5*sumlog - 8*ln(2pi) - sum_p isig*mu^2)
__device__ __forceinline__ void finalize(float* __restrict__ sm, int tid,
                                         const float* __restrict__ gbu,
                                         const float* __restrict__ gba) {
    const int g = tid >> 3, l8 = tid & 7;
    float rsum = 0.f;
    #pragma unroll
    for (int w = 0; w < 8; ++w) rsum += sm[SM_RED + 32 * 257 + w * 32 + g];
    float inv = __fdividef(1.0f, rsum + EPS);
    float nmu[2], isg[2], plog = 0.f, cpart = 0.f;
    #pragma unroll
    for (int t = 0; t < 2; ++t) {
        int p = 2 * l8 + t;
        float s1 = 0.f, s2 = 0.f;
        #pragma unroll
        for (int w = 0; w < 8; ++w) {
            s1 += sm[SM_RED + p * 257        + w * 32 + g];
            s2 += sm[SM_RED + (p + 16) * 257 + w * 32 + g];
        }
        float mu = s1 * inv;
        float sg = (s2 - 2.f * mu * s1 + mu * mu * rsum) * inv + EPS;
        sm[SM_NMU + g * 18 + p] = -mu;
        nmu[t] = -mu;
        isg[t] = __fdividef(0.5f, sg);
        plog  += __logf(sg);
        cpart  = fmaf(isg[t] * nmu[t], nmu[t], cpart);
    }
    *(u64*)(sm + SM_AT + 2 * (l8 * 32 + g)) = pack2(isg[0] * LOG2E, isg[1] * LOG2E);
    *(u64*)(sm + SM_BT + 2 * (l8 * 32 + g)) =
        pack2(2.f * isg[0] * nmu[0] * LOG2E, 2.f * isg[1] * nmu[1] * LOG2E);
    #pragma unroll
    for (int d = 1; d < 8; d <<= 1) {
        plog  += __shfl_xor_sync(0xffffffffu, plog, d);
        cpart += __shfl_xor_sync(0xffffffffu, cpart, d);
    }
    if (l8 == 0) {
        float cost = rsum * (16.f * gbu[g] + 0.5f * plog);
        float ao = __fdividef(1.f, 1.f + __expf(LAM * (cost - gba[g])));
        sm[SM_AOUT + g] = ao;
        sm[SM_CC2 + g]  = LOG2E * (__logf(ao) - 0.5f * plog - 8.f * LN2PI - cpart);
    }
}

__global__ void __launch_bounds__(NTHR, 2)
convcaps_kernel(const float* __restrict__ gx, const float* __restrict__ ga,
                const float* __restrict__ gbu, const float* __restrict__ gba,
                float* __restrict__ gout)
{
    extern __shared__ float sm[];
    const int tid  = threadIdx.x;
    const int warp = tid >> 5;
    const int c    = tid & 31;
    const int blk  = blockIdx.x;           // b*36 + h*6 + w
    const int b    = blk / 36;
    const int hw   = blk - b * 36;
    const int h2   = (hw / 6) * 2;
    const int w2   = (hw % 6) * 2;

    // ---- load pose patch duplicated: row n = [p0,p0,p1,p1,...,p15,p15] ----
    for (int idx = tid; idx < KKB * 16; idx += NTHR) {
        int n = idx >> 4, q = idx & 15;
        int ki = n / 96; int rem = n - ki * 96;
        int kj = rem >> 5; int bi = rem & 31;
        float f = gx[(size_t)((b * 14 + h2 + ki) * 14 + (w2 + kj)) * 512 + bi * 16 + q];
        *(float2*)(sm + SM_POSE + n * 32 + 2 * q) = make_float2(f, f);
    }
    for (int n = tid; n < KKB; n += NTHR) {
        int ki = n / 96; int rem = n - ki * 96;
        int kj = rem >> 5; int bi = rem & 31;
        sm[SM_ACT + n] = ga[((b * 14 + h2 + ki) * 14 + (w2 + kj)) * 32 + bi];
    }
    __syncthreads();

    u64 S1[8], S2[8];
    float rs;

    // ================= pass 0: M-step with uniform r = act/32 =================
    #pragma unroll
    for (int pp = 0; pp < 8; ++pp) { S1[pp] = 0ull; S2[pp] = 0ull; }
    rs = 0.f;
    for (int i = 0; i < 36; i += 2) {
        int n0 = warp + 8 * i, n1 = n0 + 8;
        u64 va[8], vb[8];
        compute_v2(sm, n0, c, va);
        compute_v2(sm, n1, c, vb);
        float r0 = sm[SM_ACT + n0] * (1.0f / 32.0f);
        float r1 = sm[SM_ACT + n1] * (1.0f / 32.0f);
        rs += r0 + r1;
        macc2(r0, va, S1, S2);
        macc2(r1, vb, S1, S2);
    }
    store_red(sm, warp, c, S1, S2, rs);
    __syncthreads();
    finalize(sm, tid, gbu, gba);
    __syncthreads();

    // ===== 2 fused E+M passes (2-way interleaved, A/B in REGISTERS) =====
    for (int it = 0; it < 2; ++it) {
        const float ccst2 = sm[SM_CC2 + c];
        u64 Ar[8], Br[8];
        #pragma unroll
        for (int pp = 0; pp < 8; ++pp) {
            Ar[pp] = *(const u64*)(sm + SM_AT + 2 * (pp * 32 + c));
            Br[pp] = *(const u64*)(sm + SM_BT + 2 * (pp * 32 + c));
        }
        #pragma unroll
        for (int pp = 0; pp < 8; ++pp) { S1[pp] = 0ull; S2[pp] = 0ull; }
        rs = 0.f;

        for (int i = 0; i < 36; i += 2) {
            int n0 = warp + 8 * i, n1 = n0 + 8;
            u64 va[8], vb[8];
            compute_v2(sm, n0, c, va);
            compute_v2(sm, n1, c, vb);
            float d0, d1;
            dist_pair_r(va, vb, Ar, Br, d0, d1);
            float l0 = ccst2 - d0;                 // log2 domain
            float l1 = ccst2 - d1;
            float m0 = redmax32f(l0);
            float m1 = redmax32f(l1);
            float e0 = exp2f(l0 - m0);
            float e1 = exp2f(l1 - m1);
            float s0 = redsum01(e0);
            float s1 = redsum01(e1);
            float r0 = __fdividef(e0, s0);
            float r1 = __fdividef(e1, s1);
            rs += r0 + r1;
            macc2(r0, va, S1, S2);
            macc2(r1, vb, S1, S2);
        }
        store_red(sm, warp, c, S1, S2, rs);
        __syncthreads();
        finalize(sm, tid, gbu, gba);
        __syncthreads();
    }

    // ---- outputs: p_out (288*512 floats) then a_out (288*32 floats) ----
    for (int idx = tid; idx < 512; idx += NTHR) {
        int co = idx >> 4, p = idx & 15;
        gout[(size_t)blk * 512 + idx] = -sm[SM_NMU + co * 18 + p];
    }
    if (tid < 32)
        gout[147456 + blk * 32 + tid] = sm[SM_AOUT + tid];
}

extern "C" void kernel_launch(void* const* d_in, const int* in_sizes, int n_in,
                              void* d_out, int out_size) {
    const float* x  = (const float*)d_in[0];
    const float* a  = (const float*)d_in[1];
    const float* w  = (const float*)d_in[2];
    const float* bu = (const float*)d_in[3];
    const float* ba = (const float*)d_in[4];
    float* out = (float*)d_out;
    (void)in_sizes; (void)n_in; (void)out_size;

    transpose_w_kernel<<<576, 256>>>(w);

    const int smem_bytes = SM_TOTAL * (int)sizeof(float);  // 78600 B
    cudaFuncSetAttribute(convcaps_kernel,
                         cudaFuncAttributeMaxDynamicSharedMemorySize, smem_bytes);
    convcaps_kernel<<<288, NTHR, smem_bytes>>>(x, a, bu, ba, out);
}